// round 4
// baseline (speedup 1.0000x reference)
#include <cuda_runtime.h>
#include <cstdint>

// Problem constants (fixed by the reference: B=8, S=4096, D=512, CD=4096)
#define N_ROWS 32768
#define DIM    512
#define KCODES 4096

#define BM 128
#define BN 128
#define BK 16

// Scratch (no allocation allowed in kernel_launch)
__device__ float  g_c2[KCODES];   // 0.5 * ||codebook_n||^2
__device__ int    g_enc[N_ROWS];  // argmin indices
__device__ double g_loss;         // sum of squared diffs

// ---------------------------------------------------------------------------
// packed f32x2 helpers (Blackwell FFMA2: 2x fp32 FMA per instruction)
// ---------------------------------------------------------------------------
__device__ __forceinline__ unsigned long long dup2(float v) {
    unsigned long long r;
    unsigned u = __float_as_uint(v);
    asm("mov.b64 %0, {%1,%1};" : "=l"(r) : "r"(u));
    return r;
}
__device__ __forceinline__ void ffma2(unsigned long long& acc,
                                      unsigned long long a,
                                      unsigned long long b) {
    asm("fma.rn.f32x2 %0, %1, %2, %0;" : "+l"(acc) : "l"(a), "l"(b));
}

// ---------------------------------------------------------------------------
// Kernel 0: 0.5*||c||^2 per codebook row; also zero the loss accumulator
// ---------------------------------------------------------------------------
__global__ void c2_kernel(const float* __restrict__ cb) {
    int n = blockIdx.x;
    int t = threadIdx.x;  // 128 threads
    const float* row = cb + (size_t)n * DIM;
    float s = 0.f;
    #pragma unroll
    for (int i = 0; i < DIM / 128; i++) {
        float v = row[t + i * 128];
        s += v * v;
    }
    #pragma unroll
    for (int off = 16; off > 0; off >>= 1)
        s += __shfl_down_sync(0xffffffffu, s, off);
    __shared__ float ws[4];
    if ((t & 31) == 0) ws[t >> 5] = s;
    __syncthreads();
    if (t == 0) {
        g_c2[n] = 0.5f * (ws[0] + ws[1] + ws[2] + ws[3]);
        if (n == 0) g_loss = 0.0;
    }
}

// ---------------------------------------------------------------------------
// Kernel 1: fused fp32 distance GEMM + running argmin.
// Per row we minimize s(c) = 0.5*||c||^2 - x.c  (same argmin as dist^2).
// Block: 128 rows x 128 codes tile, 256 threads (16x16), 8x8 micro-tile,
// accumulators packed f32x2 along the code (N) dimension.
// ---------------------------------------------------------------------------
__global__ __launch_bounds__(256, 2)
void argmin_kernel(const float* __restrict__ x,
                   const float* __restrict__ cb,
                   float* __restrict__ out_enc) {
    __shared__ __align__(16) float As[BK][BM];  // k-major: As[k][m]
    __shared__ __align__(16) float Bs[BK][BN];  // k-major: Bs[k][n]
    __shared__ float Cs[BN];                    // 0.5*||c||^2 for this tile

    const int t  = threadIdx.x;
    const int tx = t & 15;   // code-dim thread coord (8 cols each)
    const int ty = t >> 4;   // row-dim thread coord (8 rows each)
    const int m0 = blockIdx.x * BM;

    float best_d[8];
    int   best_i[8];
    #pragma unroll
    for (int i = 0; i < 8; i++) { best_d[i] = 3.4e38f; best_i[i] = 0; }

    for (int nt = 0; nt < KCODES / BN; nt++) {
        const int n0 = nt * BN;

        unsigned long long acc[8][4];
        #pragma unroll
        for (int i = 0; i < 8; i++)
            #pragma unroll
            for (int j = 0; j < 4; j++) acc[i][j] = 0ull;

        for (int kc = 0; kc < DIM / BK; kc++) {
            const int kt = kc * BK;
            __syncthreads();  // previous tile's smem fully consumed

            // Stage A (x rows) and B (codebook rows), transposing to k-major.
            #pragma unroll
            for (int r2 = 0; r2 < 2; r2++) {
                int idx = t + r2 * 256;      // 0..511
                int row = idx >> 2;          // 0..127
                int q   = idx & 3;           // float4 slot within BK=16
                float4 fa = *(const float4*)(x  + (size_t)(m0 + row) * DIM + kt + q * 4);
                As[q * 4 + 0][row] = fa.x; As[q * 4 + 1][row] = fa.y;
                As[q * 4 + 2][row] = fa.z; As[q * 4 + 3][row] = fa.w;
                float4 fb = *(const float4*)(cb + (size_t)(n0 + row) * DIM + kt + q * 4);
                Bs[q * 4 + 0][row] = fb.x; Bs[q * 4 + 1][row] = fb.y;
                Bs[q * 4 + 2][row] = fb.z; Bs[q * 4 + 3][row] = fb.w;
            }
            if (kc == 0 && t < BN) Cs[t] = g_c2[n0 + t];
            __syncthreads();

            #pragma unroll
            for (int kk = 0; kk < BK; kk++) {
                float4 a0 = *(const float4*)&As[kk][ty * 8];
                float4 a1 = *(const float4*)&As[kk][ty * 8 + 4];
                double2 bd0 = *(const double2*)&Bs[kk][tx * 8];
                double2 bd1 = *(const double2*)&Bs[kk][tx * 8 + 4];
                unsigned long long bv[4];
                bv[0] = __double_as_longlong(bd0.x);
                bv[1] = __double_as_longlong(bd0.y);
                bv[2] = __double_as_longlong(bd1.x);
                bv[3] = __double_as_longlong(bd1.y);
                float av[8] = {a0.x, a0.y, a0.z, a0.w, a1.x, a1.y, a1.z, a1.w};
                #pragma unroll
                for (int i = 0; i < 8; i++) {
                    unsigned long long aa = dup2(av[i]);
                    ffma2(acc[i][0], aa, bv[0]);
                    ffma2(acc[i][1], aa, bv[1]);
                    ffma2(acc[i][2], aa, bv[2]);
                    ffma2(acc[i][3], aa, bv[3]);
                }
            }
        }

        // Fold this code tile into the running per-row best.
        #pragma unroll
        for (int i = 0; i < 8; i++) {
            #pragma unroll
            for (int j = 0; j < 4; j++) {
                float lo = __uint_as_float((unsigned)(acc[i][j] & 0xffffffffull));
                float hi = __uint_as_float((unsigned)(acc[i][j] >> 32));
                int c0 = tx * 8 + 2 * j;
                float s0 = Cs[c0]     - lo;
                float s1 = Cs[c0 + 1] - hi;
                if (s0 < best_d[i]) { best_d[i] = s0; best_i[i] = n0 + c0; }
                if (s1 < best_d[i]) { best_d[i] = s1; best_i[i] = n0 + c0 + 1; }
            }
        }
    }

    // Reduce across the 16 tx-threads sharing the same 8 rows (16-lane segments).
    #pragma unroll
    for (int i = 0; i < 8; i++) {
        float d = best_d[i];
        int   bi = best_i[i];
        #pragma unroll
        for (int off = 8; off > 0; off >>= 1) {
            float od = __shfl_down_sync(0xffffffffu, d, off, 16);
            int   oi = __shfl_down_sync(0xffffffffu, bi, off, 16);
            if (od < d || (od == d && oi < bi)) { d = od; bi = oi; }
        }
        if (tx == 0) {
            int row = m0 + ty * 8 + i;
            g_enc[row]   = bi;
            out_enc[row] = (float)bi;
        }
    }
}

// ---------------------------------------------------------------------------
// Kernel 2: gather nearest = codebook[enc] and accumulate sum of (x-nearest)^2.
// NOTE: out_near base is only 8-byte aligned (d_out + 32770 floats), so all
// stores to it go through float2 (STG.64). Loads from x/cb stay float4.
// ---------------------------------------------------------------------------
__global__ void gather_loss_kernel(const float* __restrict__ x,
                                   const float* __restrict__ cb,
                                   float* __restrict__ out_near) {
    int row = blockIdx.x;   // 32768 blocks
    int t   = threadIdx.x;  // 128 threads, DIM/4 = 128 float4 per row
    int enc = g_enc[row];
    const float4* cr   = (const float4*)(cb + (size_t)enc * DIM);
    const float4* xr   = (const float4*)(x  + (size_t)row * DIM);
    float2*       orow = (float2*)(out_near + (size_t)row * DIM);

    float4 c  = cr[t];
    float4 xv = xr[t];
    orow[2 * t]     = make_float2(c.x, c.y);
    orow[2 * t + 1] = make_float2(c.z, c.w);
    float dx = xv.x - c.x, dy = xv.y - c.y, dz = xv.z - c.z, dw = xv.w - c.w;
    float s = dx * dx + dy * dy + dz * dz + dw * dw;

    #pragma unroll
    for (int off = 16; off > 0; off >>= 1)
        s += __shfl_down_sync(0xffffffffu, s, off);
    __shared__ float ws[4];
    if ((t & 31) == 0) ws[t >> 5] = s;
    __syncthreads();
    if (t == 0) {
        double tot = (double)ws[0] + (double)ws[1] + (double)ws[2] + (double)ws[3];
        atomicAdd(&g_loss, tot);
    }
}

// ---------------------------------------------------------------------------
// Kernel 3: finalize both losses (identical in forward: stop_gradient is id)
// ---------------------------------------------------------------------------
__global__ void finalize_kernel(float* __restrict__ out_losses) {
    double mean = g_loss / ((double)N_ROWS * (double)DIM);
    out_losses[0] = (float)mean;  // codebook_loss
    out_losses[1] = (float)mean;  // encoder_loss
}

// ---------------------------------------------------------------------------
// Launch. Output layout (float32, reference tuple order, flattened):
//   [0, 32768)                encoding (as float)
//   [32768, 32770)            codebook_loss, encoder_loss
//   [32770, 32770+32768*512)  nearest
// ---------------------------------------------------------------------------
extern "C" void kernel_launch(void* const* d_in, const int* in_sizes, int n_in,
                              void* d_out, int out_size) {
    const float* x  = (const float*)d_in[0];
    const float* cb = (const float*)d_in[1];
    // Robustness: if the harness orders inputs differently, detect by size.
    if (n_in >= 2 && in_sizes[0] == KCODES * DIM && in_sizes[1] == N_ROWS * DIM) {
        const float* tmp = x; x = cb; cb = tmp;
    }

    float* out        = (float*)d_out;
    float* out_enc    = out;
    float* out_losses = out + N_ROWS;
    float* out_near   = out + N_ROWS + 2;

    c2_kernel<<<KCODES, 128>>>(cb);
    argmin_kernel<<<N_ROWS / BM, 256>>>(x, cb, out_enc);
    gather_loss_kernel<<<N_ROWS, 128>>>(x, cb, out_near);
    finalize_kernel<<<1, 1>>>(out_losses);
}

// round 6
// speedup vs baseline: 5.3398x; 5.3398x over previous
#include <cuda_runtime.h>
#include <cuda_bf16.h>
#include <cstdint>

// Problem constants (fixed: B=8, S=4096, D=512, CD=4096)
#define N_ROWS 32768
#define DIM    512
#define KCODES 4096

// main kernel tiling
#define M_CTA   128                 // rows per CTA
#define N_TILE  128                 // codes per B stage
#define BK      64                  // bf16 K per chunk (128B rows)
#define NT      (KCODES / N_TILE)   // 32 code tiles
#define CHUNKS  (DIM / BK)          // 8 k-chunks
#define ITERS   (NT * CHUNKS)       // 256
#define GRID    (N_ROWS / M_CTA)    // 256
#define NTHR    256

// smem: [align 1KB][A_full 128KB][B 3x16KB][merge 8KB]
#define A_BYTES   (M_CTA * DIM * 2)          // 131072
#define BSTAGE    (N_TILE * BK * 2)          // 16384
#define MERGE_OFF (A_BYTES + 3 * BSTAGE)     // 180224
#define DYN_SMEM  (1024 + MERGE_OFF + 8192)  // 189440

// Scratch (device globals; no allocation allowed)
__device__ __align__(16) float  g_c2[KCODES];        // 0.5*||c||^2 exact fp32
__device__ int    g_cand[N_ROWS * 4];                // top-4 approx candidates
__device__ double g_loss;
__device__ __align__(16) __nv_bfloat16 g_xb[N_ROWS * DIM];   // 32MB
__device__ __align__(16) __nv_bfloat16 g_cbb[KCODES * DIM];  // 4MB

// ---------------------------------------------------------------------------
// PTX helpers (sm_80-level only: cp.async, ldmatrix, mma.sync)
// ---------------------------------------------------------------------------
__device__ __forceinline__ uint32_t smem_u32(const void* p) {
    uint32_t a;
    asm("{ .reg .u64 t; cvta.to.shared.u64 t, %1; cvt.u32.u64 %0, t; }"
        : "=r"(a) : "l"(p));
    return a;
}

#define CP16(dst, src) \
    asm volatile("cp.async.cg.shared.global [%0], [%1], 16;" \
                 :: "r"(dst), "l"(src) : "memory")

#define LDSM4(r0, r1, r2, r3, addr) \
    asm volatile("ldmatrix.sync.aligned.m8n8.x4.shared.b16 {%0,%1,%2,%3}, [%4];" \
                 : "=r"(r0), "=r"(r1), "=r"(r2), "=r"(r3) : "r"(addr))

#define MMA16816(d, a, b) \
    asm volatile("mma.sync.aligned.m16n8k16.row.col.f32.bf16.bf16.f32 " \
                 "{%0,%1,%2,%3}, {%4,%5,%6,%7}, {%8,%9}, {%0,%1,%2,%3};" \
                 : "+f"((d)[0]), "+f"((d)[1]), "+f"((d)[2]), "+f"((d)[3]) \
                 : "r"((a)[0]), "r"((a)[1]), "r"((a)[2]), "r"((a)[3]), \
                   "r"((b)[0]), "r"((b)[1]))

// sorted ascending top-4 insert (all indices constant after unroll -> regs)
__device__ __forceinline__ void t4_insert(float (&v)[4], int (&ix)[4],
                                          float s, int i) {
    if (s < v[3]) {
        if (s < v[1]) {
            if (s < v[0]) {
                v[3]=v[2]; ix[3]=ix[2]; v[2]=v[1]; ix[2]=ix[1];
                v[1]=v[0]; ix[1]=ix[0]; v[0]=s; ix[0]=i;
            } else {
                v[3]=v[2]; ix[3]=ix[2]; v[2]=v[1]; ix[2]=ix[1];
                v[1]=s; ix[1]=i;
            }
        } else {
            if (s < v[2]) { v[3]=v[2]; ix[3]=ix[2]; v[2]=s; ix[2]=i; }
            else          { v[3]=s; ix[3]=i; }
        }
    }
}

// ---------------------------------------------------------------------------
// Prep kernels: bf16 conversion + 0.5||c||^2 + loss zero
// ---------------------------------------------------------------------------
__global__ void prep_x(const float* __restrict__ x) {
    int i = blockIdx.x * blockDim.x + threadIdx.x;  // 8192 x 512 = 4,194,304
    float4 v = ((const float4*)x)[i];
    __nv_bfloat162 lo = __float22bfloat162_rn(make_float2(v.x, v.y));
    __nv_bfloat162 hi = __float22bfloat162_rn(make_float2(v.z, v.w));
    uint2 pk;
    pk.x = *(uint32_t*)&lo;
    pk.y = *(uint32_t*)&hi;
    ((uint2*)g_xb)[i] = pk;
}

__global__ void prep_cb(const float* __restrict__ cb) {
    int n = blockIdx.x, t = threadIdx.x;  // 4096 x 128
    float4 v = ((const float4*)(cb + (size_t)n * DIM))[t];
    __nv_bfloat162 lo = __float22bfloat162_rn(make_float2(v.x, v.y));
    __nv_bfloat162 hi = __float22bfloat162_rn(make_float2(v.z, v.w));
    uint2 pk;
    pk.x = *(uint32_t*)&lo;
    pk.y = *(uint32_t*)&hi;
    ((uint2*)g_cbb)[(size_t)n * 128 + t] = pk;

    float s = v.x * v.x + v.y * v.y + v.z * v.z + v.w * v.w;
    #pragma unroll
    for (int off = 16; off > 0; off >>= 1)
        s += __shfl_down_sync(0xffffffffu, s, off);
    __shared__ float ws[4];
    if ((t & 31) == 0) ws[t >> 5] = s;
    __syncthreads();
    if (t == 0) {
        g_c2[n] = 0.5f * (ws[0] + ws[1] + ws[2] + ws[3]);
        if (n == 0) g_loss = 0.0;
    }
}

// ---------------------------------------------------------------------------
// Kernel 1: bf16 HMMA distance GEMM + fused per-row top-4 candidates.
// Score(row, code) = 0.5||c||^2 - x.c (same argmin ordering as dist^2).
// A (128 rows x 512 K) resident in smem; B streamed in 3-stage cp.async ring.
// ---------------------------------------------------------------------------
__global__ __launch_bounds__(NTHR)
void cand_kernel(float* __restrict__ dummy) {
    extern __shared__ char dsm[];
    const uint32_t sraw = smem_u32(dsm);
    const uint32_t sb   = (sraw + 1023u) & ~1023u;
    char* base = dsm + (sb - sraw);
    const uint32_t Ab = sb;
    const uint32_t Bb = sb + A_BYTES;

    const int tid  = threadIdx.x;
    const int lane = tid & 31, wid = tid >> 5;
    const int warpM = wid & 3, warpN = wid >> 2;
    const int m0 = blockIdx.x * M_CTA;

    // ldmatrix per-thread address constants
    const uint32_t arow = (uint32_t)((lane & 7) + ((lane & 8) ? 8 : 0));
    const uint32_t asel = (lane & 16) ? 16u : 0u;
    const uint32_t axr  = (arow & 7u) << 4;
    const uint32_t abase0 = (uint32_t)(warpM * 32 + (int)arow) * 128u;
    const uint32_t abase1 = abase0 + 16u * 128u;
    const uint32_t brow = (uint32_t)((lane & 7) + ((lane & 16) ? 8 : 0));
    const uint32_t bsel = (lane & 8) ? 16u : 0u;
    const uint32_t bxr  = (brow & 7u) << 4;
    const uint32_t bstart = (uint32_t)(warpN * 64 + (int)brow) * 128u;

    // ---- prologue: stage A fully (group 0), B it=0 (g1), B it=1 (g2) ------
    {
        #pragma unroll
        for (int j = 0; j < 32; j++) {
            int e = tid + j * 256;
            int ch = e >> 10, rem = e & 1023, row = rem >> 3, seg = rem & 7;
            const __nv_bfloat16* src =
                g_xb + (size_t)(m0 + row) * DIM + ch * BK + seg * 8;
            uint32_t dst = Ab + (uint32_t)ch * 16384u + (uint32_t)row * 128u +
                           (((uint32_t)seg * 16u) ^ (((uint32_t)row & 7u) << 4));
            CP16(dst, src);
        }
        asm volatile("cp.async.commit_group;" ::: "memory");
        #pragma unroll
        for (int pre = 0; pre < 2; pre++) {
            int nt2 = pre >> 3, kc2 = pre & 7, s2 = pre % 3;
            #pragma unroll
            for (int j = 0; j < 4; j++) {
                int e = tid + j * 256;
                int row = e >> 3, seg = e & 7;
                const __nv_bfloat16* src =
                    g_cbb + (size_t)(nt2 * N_TILE + row) * DIM + kc2 * BK + seg * 8;
                uint32_t dst = Bb + (uint32_t)s2 * BSTAGE + (uint32_t)row * 128u +
                               (((uint32_t)seg * 16u) ^ (((uint32_t)row & 7u) << 4));
                CP16(dst, src);
            }
            asm volatile("cp.async.commit_group;" ::: "memory");
        }
    }

    float acc[2][8][4];
    #pragma unroll
    for (int mt = 0; mt < 2; mt++)
        #pragma unroll
        for (int p = 0; p < 8; p++)
            #pragma unroll
            for (int c = 0; c < 4; c++) acc[mt][p][c] = 0.f;

    float t4v[4][4];
    int   t4i[4][4];
    #pragma unroll
    for (int r = 0; r < 4; r++)
        #pragma unroll
        for (int j = 0; j < 4; j++) { t4v[r][j] = 3.4e38f; t4i[r][j] = 0; }

    // ---- main loop ---------------------------------------------------------
    for (int it = 0; it < ITERS; it++) {
        const int nt = it >> 3, kc = it & 7, s = it % 3;
        asm volatile("cp.async.wait_group 1;" ::: "memory");
        __syncthreads();

        // prefetch B for it+2 into stage (it+2)%3
        const int it2 = it + 2;
        if (it2 < ITERS) {
            const int nt2 = it2 >> 3, kc2 = it2 & 7, s2 = it2 % 3;
            #pragma unroll
            for (int j = 0; j < 4; j++) {
                int e = tid + j * 256;
                int row = e >> 3, seg = e & 7;
                const __nv_bfloat16* src =
                    g_cbb + (size_t)(nt2 * N_TILE + row) * DIM + kc2 * BK + seg * 8;
                uint32_t dst = Bb + (uint32_t)s2 * BSTAGE + (uint32_t)row * 128u +
                               (((uint32_t)seg * 16u) ^ (((uint32_t)row & 7u) << 4));
                CP16(dst, src);
            }
        }
        asm volatile("cp.async.commit_group;" ::: "memory");

        // compute this chunk
        const uint32_t Achunk = Ab + (uint32_t)kc * 16384u;
        const uint32_t Bs     = Bb + (uint32_t)s * BSTAGE;
        #pragma unroll
        for (int ks = 0; ks < 4; ks++) {
            const uint32_t koA = (((uint32_t)(ks * 32)) + asel) ^ axr;
            uint32_t a0[4], a1[4];
            LDSM4(a0[0], a0[1], a0[2], a0[3], Achunk + abase0 + koA);
            LDSM4(a1[0], a1[1], a1[2], a1[3], Achunk + abase1 + koA);
            const uint32_t koB = (((uint32_t)(ks * 32)) + bsel) ^ bxr;
            uint32_t bb[8][2];
            #pragma unroll
            for (int p = 0; p < 4; p++) {
                uint32_t r0, r1, r2, r3;
                LDSM4(r0, r1, r2, r3, Bs + bstart + (uint32_t)p * 2048u + koB);
                bb[2 * p][0] = r0; bb[2 * p][1] = r1;
                bb[2 * p + 1][0] = r2; bb[2 * p + 1][1] = r3;
            }
            #pragma unroll
            for (int p = 0; p < 8; p++) {
                MMA16816(acc[0][p], a0, bb[p]);
                MMA16816(acc[1][p], a1, bb[p]);
            }
        }

        // fold finished code tile into running top-4, reset accumulators
        if (kc == 7) {
            #pragma unroll
            for (int mt = 0; mt < 2; mt++) {
                #pragma unroll
                for (int p = 0; p < 8; p++) {
                    const int ng = nt * N_TILE + warpN * 64 + p * 8 + 2 * (lane & 3);
                    const float2 c2 = __ldg((const float2*)(g_c2 + ng));
                    t4_insert(t4v[mt * 2 + 0], t4i[mt * 2 + 0], c2.x - acc[mt][p][0], ng);
                    t4_insert(t4v[mt * 2 + 0], t4i[mt * 2 + 0], c2.y - acc[mt][p][1], ng + 1);
                    t4_insert(t4v[mt * 2 + 1], t4i[mt * 2 + 1], c2.x - acc[mt][p][2], ng);
                    t4_insert(t4v[mt * 2 + 1], t4i[mt * 2 + 1], c2.y - acc[mt][p][3], ng + 1);
                    acc[mt][p][0] = 0.f; acc[mt][p][1] = 0.f;
                    acc[mt][p][2] = 0.f; acc[mt][p][3] = 0.f;
                }
            }
        }
    }

    // ---- merge: quad (shfl) -> cross-warpN (smem) --------------------------
    #pragma unroll
    for (int rs = 0; rs < 4; rs++) {
        #pragma unroll
        for (int delta = 1; delta <= 2; delta <<= 1) {
            float ov[4]; int oi[4];
            #pragma unroll
            for (int j = 0; j < 4; j++) {
                ov[j] = __shfl_xor_sync(0xffffffffu, t4v[rs][j], delta);
                oi[j] = __shfl_xor_sync(0xffffffffu, t4i[rs][j], delta);
            }
            #pragma unroll
            for (int j = 0; j < 4; j++) t4_insert(t4v[rs], t4i[rs], ov[j], oi[j]);
        }
    }

    __syncthreads();  // compute fully done; reuse B-stage smem for merge bufs
    float* mv = (float*)(base + MERGE_OFF - 49152);  // alias over B stages
    int*   mi = (int*)(base + MERGE_OFF - 49152 + 4096);
    if ((lane & 3) == 0) {
        #pragma unroll
        for (int rs = 0; rs < 4; rs++) {
            int row_local = warpM * 32 + (rs >> 1) * 16 + ((rs & 1) << 3) + (lane >> 2);
            int idx = (warpN * 128 + row_local) * 4;
            #pragma unroll
            for (int j = 0; j < 4; j++) { mv[idx + j] = t4v[rs][j]; mi[idx + j] = t4i[rs][j]; }
        }
    }
    __syncthreads();
    if (tid < 128) {
        float v[4]; int ix[4];
        #pragma unroll
        for (int j = 0; j < 4; j++) { v[j] = mv[tid * 4 + j]; ix[j] = mi[tid * 4 + j]; }
        #pragma unroll
        for (int j = 0; j < 4; j++)
            t4_insert(v, ix, mv[(128 + tid) * 4 + j], mi[(128 + tid) * 4 + j]);
        #pragma unroll
        for (int j = 0; j < 4; j++) g_cand[(size_t)(m0 + tid) * 4 + j] = ix[j];
    }
    (void)dummy;
}

// ---------------------------------------------------------------------------
// Kernel 2: exact fp32 rescore of 4 candidates, argmin (tie -> lower index),
// gather nearest, accumulate loss. out_near base only 8B aligned -> float2.
// ---------------------------------------------------------------------------
__global__ void rescore_gather_kernel(const float* __restrict__ x,
                                      const float* __restrict__ cb,
                                      float* __restrict__ out_enc,
                                      float* __restrict__ out_near) {
    const int row = blockIdx.x;   // 32768
    const int t   = threadIdx.x;  // 128
    __shared__ float sdot[4][4];
    __shared__ int   s_enc;
    __shared__ float ws[4];

    int cand[4];
    #pragma unroll
    for (int j = 0; j < 4; j++) cand[j] = g_cand[(size_t)row * 4 + j];

    const float4 xv = ((const float4*)(x + (size_t)row * DIM))[t];
    #pragma unroll
    for (int j = 0; j < 4; j++) {
        const float4 cv = ((const float4*)(cb + (size_t)cand[j] * DIM))[t];
        float p = xv.x * cv.x + xv.y * cv.y + xv.z * cv.z + xv.w * cv.w;
        #pragma unroll
        for (int off = 16; off > 0; off >>= 1)
            p += __shfl_down_sync(0xffffffffu, p, off);
        if ((t & 31) == 0) sdot[t >> 5][j] = p;
    }
    __syncthreads();
    if (t == 0) {
        float bs = 3.4e38f; int bi = 0x7fffffff;
        #pragma unroll
        for (int j = 0; j < 4; j++) {
            float dot = sdot[0][j] + sdot[1][j] + sdot[2][j] + sdot[3][j];
            float s = g_c2[cand[j]] - dot;
            if (s < bs || (s == bs && cand[j] < bi)) { bs = s; bi = cand[j]; }
        }
        s_enc = bi;
        out_enc[row] = (float)bi;
    }
    __syncthreads();
    const int enc = s_enc;

    const float4 c = ((const float4*)(cb + (size_t)enc * DIM))[t];
    float2* orow = (float2*)(out_near + (size_t)row * DIM);
    orow[2 * t]     = make_float2(c.x, c.y);
    orow[2 * t + 1] = make_float2(c.z, c.w);
    float dx = xv.x - c.x, dy = xv.y - c.y, dz = xv.z - c.z, dw = xv.w - c.w;
    float s = dx * dx + dy * dy + dz * dz + dw * dw;
    #pragma unroll
    for (int off = 16; off > 0; off >>= 1)
        s += __shfl_down_sync(0xffffffffu, s, off);
    if ((t & 31) == 0) ws[t >> 5] = s;
    __syncthreads();
    if (t == 0) {
        double tot = (double)ws[0] + (double)ws[1] + (double)ws[2] + (double)ws[3];
        atomicAdd(&g_loss, tot);
    }
}

__global__ void finalize_kernel(float* __restrict__ out_losses) {
    double mean = g_loss / ((double)N_ROWS * (double)DIM);
    out_losses[0] = (float)mean;
    out_losses[1] = (float)mean;
}

// ---------------------------------------------------------------------------
// Output layout (float32): [0,32768) encoding; [32768,32770) losses;
// [32770, ...) nearest (base only 8B aligned).
// ---------------------------------------------------------------------------
extern "C" void kernel_launch(void* const* d_in, const int* in_sizes, int n_in,
                              void* d_out, int out_size) {
    const float* x  = (const float*)d_in[0];
    const float* cb = (const float*)d_in[1];
    if (n_in >= 2 && in_sizes[0] == KCODES * DIM && in_sizes[1] == N_ROWS * DIM) {
        const float* tmp = x; x = cb; cb = tmp;
    }

    float* out        = (float*)d_out;
    float* out_enc    = out;
    float* out_losses = out + N_ROWS;
    float* out_near   = out + N_ROWS + 2;

    static int smem_set = 0;
    if (!smem_set) {
        cudaFuncSetAttribute(cand_kernel,
                             cudaFuncAttributeMaxDynamicSharedMemorySize, DYN_SMEM);
        smem_set = 1;
    }

    prep_x<<<8192, 512>>>(x);
    prep_cb<<<KCODES, 128>>>(cb);
    cand_kernel<<<GRID, NTHR, DYN_SMEM>>>(out);
    rescore_gather_kernel<<<N_ROWS, 128>>>(x, cb, out_enc, out_near);
    finalize_kernel<<<1, 1>>>(out_losses);
}